// round 5
// baseline (speedup 1.0000x reference)
#include <cuda_runtime.h>
#include <cuda_bf16.h>
#include <cstdint>

// ---------------------------------------------------------------------------
// Problem constants
// ---------------------------------------------------------------------------
#define BATCH   128
#define CCH     256
#define HWSZ    784
#define KTOT    200704          // 256*784
#define CHUNK_K 64              // fp32 elements per row per chunk
#define TOTCH   3136            // KTOT / 64
#define GRIDX   148             // 148*21 + 28 = 3136
#define LDPAD   72              // bf16 per padded SMEM row (144 B)

// Device-global scratch (atomically accumulated; zeroed each call)
__device__ float g_gram[2][BATCH][BATCH];
__device__ float g_pool[2][BATCH][CCH];
__device__ float g_gate[2][BATCH][CCH];

// ---------------------------------------------------------------------------
// Helpers
// ---------------------------------------------------------------------------
__device__ __forceinline__ uint32_t smem_u32(const void* p) {
    uint32_t a;
    asm("{ .reg .u64 t; cvta.to.shared.u64 t, %1; cvt.u32.u64 %0, t; }"
        : "=r"(a) : "l"(p));
    return a;
}
__device__ __forceinline__ void ldm4(uint32_t a[4], uint32_t addr) {
    asm volatile("ldmatrix.sync.aligned.m8n8.x4.shared.b16 {%0,%1,%2,%3}, [%4];"
        : "=r"(a[0]), "=r"(a[1]), "=r"(a[2]), "=r"(a[3]) : "r"(addr));
}
__device__ __forceinline__ void mma16816(float c[4], const uint32_t a[4],
                                         const uint32_t b0, const uint32_t b1) {
    asm volatile(
        "mma.sync.aligned.m16n8k16.row.col.f32.bf16.bf16.f32 "
        "{%0,%1,%2,%3}, {%4,%5,%6,%7}, {%8,%9}, {%0,%1,%2,%3};"
        : "+f"(c[0]), "+f"(c[1]), "+f"(c[2]), "+f"(c[3])
        : "r"(a[0]), "r"(a[1]), "r"(a[2]), "r"(a[3]), "r"(b0), "r"(b1));
}

// ---------------------------------------------------------------------------
// Kernel 0: zero scratch (g_gram + g_pool = 65536 floats)
// ---------------------------------------------------------------------------
__global__ void zero_kernel() {
    int i = blockIdx.x * 256 + threadIdx.x;
    if (i < 2 * BATCH * BATCH) (&g_gram[0][0][0])[i] = 0.f;
    (&g_pool[0][0][0])[i] = 0.f;
}

// ---------------------------------------------------------------------------
// Kernel 1: Gram (symmetric-aware) + fused pooling.
//   grid (148, 2): blockIdx.y = matrix. Each CTA: 21-22 strided chunks of
//   [128 rows x 64 fp32] -> bf16 SMEM tile, used as both A and B.
//   Warp w computes: strip rows [16w,16w+16) x cols [0,64)   (8 m16n8 tiles)
//                  + Q11 tile  rows [64+16*(w>>1)) x cols [64+32*(w&1), +32)
//   Q10 (w>=4 strips) is mirrored into Q01 in the epilogue.
//   => 96 of 128 m16n8 tiles per k-step, 12 per warp (balanced).
// ---------------------------------------------------------------------------
__global__ __launch_bounds__(256, 2)
void gram_kernel(const float* __restrict__ s, const float* __restrict__ t) {
    __shared__ __nv_bfloat16 tile[2][BATCH][LDPAD];

    const int mat  = blockIdx.y;
    const float* F = mat ? t : s;
    const int tid  = threadIdx.x;
    const int lane = tid & 31;
    const int wid  = tid >> 5;
    const int row  = tid >> 1;
    const int half = tid & 1;
    const float* rowp = F + (size_t)row * KTOT;

    const int nchunk = 21 + (blockIdx.x < (TOTCH - GRIDX * 21));

    float accm[8][4];                    // main strip: 8 n8-tiles
    float accd[4][4];                    // Q11 quarter: 4 n8-tiles
    #pragma unroll
    for (int i = 0; i < 8; i++)
        #pragma unroll
        for (int r = 0; r < 4; r++) accm[i][r] = 0.f;
    #pragma unroll
    for (int i = 0; i < 4; i++)
        #pragma unroll
        for (int r = 0; r < 4; r++) accd[i][r] = 0.f;

    // ldmatrix addresses (precomputed, bf16-index based; bytes = *2)
    const int a_row  = (lane & 15);
    const int a_colo = (lane >> 4) * 8;
    const int b_q    = lane >> 3;             // 0..3
    const int b_wi   = lane & 7;
    const int b_rowo = (b_q >> 1) * 8 + b_wi; // row offset within n16 group
    const int b_colo = (b_q & 1) * 8;

    // pooling state
    float pacc = 0.f;
    int   pch  = -1;

    // prefetch chunk 0 (fp32 -> bf16 regs, fp32 pooling)
    uint2 pf[8];
    {
        int kb = blockIdx.x * CHUNK_K + half * 32;
        #pragma unroll
        for (int j = 0; j < 8; j++) {
            int kk = kb + j * 4;
            float4 v = *(const float4*)(rowp + kk);
            int ch = kk / HWSZ;
            if (ch != pch) {
                if (pch >= 0) atomicAdd(&g_pool[mat][row][pch], pacc);
                pacc = 0.f; pch = ch;
            }
            pacc += (v.x + v.y) + (v.z + v.w);
            __nv_bfloat162 p0 = __float22bfloat162_rn(make_float2(v.x, v.y));
            __nv_bfloat162 p1 = __float22bfloat162_rn(make_float2(v.z, v.w));
            pf[j] = make_uint2(*(uint32_t*)&p0, *(uint32_t*)&p1);
        }
    }

    const int mS = wid * 16;                       // main strip row base
    const int mD = 64 + (wid >> 1) * 16;           // Q11 row base
    const int nD = 64 + (wid & 1) * 32;            // Q11 col base

    for (int c = 0; c < nchunk; c++) {
        const int buf = c & 1;
        // store prefetched bf16 chunk
        #pragma unroll
        for (int j = 0; j < 8; j++)
            *(uint2*)&tile[buf][row][half * 32 + j * 4] = pf[j];
        __syncthreads();   // single barrier: store-visible + prev compute on buf done

        // prefetch next chunk (LDG latency overlaps MMA work below)
        if (c + 1 < nchunk) {
            int kb = (blockIdx.x + (c + 1) * GRIDX) * CHUNK_K + half * 32;
            #pragma unroll
            for (int j = 0; j < 8; j++) {
                int kk = kb + j * 4;
                float4 v = *(const float4*)(rowp + kk);
                int ch = kk / HWSZ;
                if (ch != pch) {
                    atomicAdd(&g_pool[mat][row][pch], pacc);
                    pacc = 0.f; pch = ch;
                }
                pacc += (v.x + v.y) + (v.z + v.w);
                __nv_bfloat162 p0 = __float22bfloat162_rn(make_float2(v.x, v.y));
                __nv_bfloat162 p1 = __float22bfloat162_rn(make_float2(v.z, v.w));
                pf[j] = make_uint2(*(uint32_t*)&p0, *(uint32_t*)&p1);
            }
        }

        const uint32_t base = smem_u32(&tile[buf][0][0]);
        #pragma unroll
        for (int ks = 0; ks < 4; ks++) {
            const int kc = ks * 16;
            uint32_t am[4], ad[4];
            ldm4(am, base + (uint32_t)((mS + a_row) * LDPAD + kc + a_colo) * 2u);
            ldm4(ad, base + (uint32_t)((mD + a_row) * LDPAD + kc + a_colo) * 2u);

            // main strip B: 8 n8 tiles at n=0..56 (4 x ldmatrix.x4)
            #pragma unroll
            for (int p = 0; p < 4; p++) {
                uint32_t b[4];
                ldm4(b, base + (uint32_t)((p * 16 + b_rowo) * LDPAD + kc + b_colo) * 2u);
                mma16816(accm[2 * p],     am, b[0], b[1]);
                mma16816(accm[2 * p + 1], am, b[2], b[3]);
            }
            // Q11 B: 4 n8 tiles at nD..nD+24 (2 x ldmatrix.x4)
            #pragma unroll
            for (int p = 0; p < 2; p++) {
                uint32_t b[4];
                ldm4(b, base + (uint32_t)((nD + p * 16 + b_rowo) * LDPAD + kc + b_colo) * 2u);
                mma16816(accd[2 * p],     ad, b[0], b[1]);
                mma16816(accd[2 * p + 1], ad, b[2], b[3]);
            }
        }
    }

    // flush pooling remainder
    if (pch >= 0) atomicAdd(&g_pool[mat][row][pch], pacc);

    // epilogue: atomic-reduce partial tiles into g_gram (+ mirror for Q10)
    const int mrow = lane >> 2;
    const int nc2  = (lane & 3) * 2;
    #pragma unroll
    for (int ti = 0; ti < 8; ti++) {
        const int n0 = ti * 8;
        const int m0 = mS + mrow, m1 = mS + mrow + 8;
        const int n1 = n0 + nc2;
        atomicAdd(&g_gram[mat][m0][n1],     accm[ti][0]);
        atomicAdd(&g_gram[mat][m0][n1 + 1], accm[ti][1]);
        atomicAdd(&g_gram[mat][m1][n1],     accm[ti][2]);
        atomicAdd(&g_gram[mat][m1][n1 + 1], accm[ti][3]);
        if (wid >= 4) {                       // Q10 -> mirror into Q01
            atomicAdd(&g_gram[mat][n1][m0],     accm[ti][0]);
            atomicAdd(&g_gram[mat][n1 + 1][m0], accm[ti][1]);
            atomicAdd(&g_gram[mat][n1][m1],     accm[ti][2]);
            atomicAdd(&g_gram[mat][n1 + 1][m1], accm[ti][3]);
        }
    }
    #pragma unroll
    for (int ti = 0; ti < 4; ti++) {
        const int n1 = nD + ti * 8 + nc2;
        atomicAdd(&g_gram[mat][mD + mrow][n1],         accd[ti][0]);
        atomicAdd(&g_gram[mat][mD + mrow][n1 + 1],     accd[ti][1]);
        atomicAdd(&g_gram[mat][mD + mrow + 8][n1],     accd[ti][2]);
        atomicAdd(&g_gram[mat][mD + mrow + 8][n1 + 1], accd[ti][3]);
    }
}

// ---------------------------------------------------------------------------
// Kernel 2: normalize + z + 6 MLPs -> gates. 32 CTAs x 4 batch rows.
// Warp-cooperative dot products (coalesced weight reads).
// ---------------------------------------------------------------------------
__device__ __forceinline__ float warp_sum(float v) {
    #pragma unroll
    for (int o = 16; o; o >>= 1) v += __shfl_xor_sync(0xFFFFFFFFu, v, o);
    return v;
}

__device__ __forceinline__ void run_mlp(
    const float* __restrict__ w1, const float* __restrict__ b1,
    const float* __restrict__ w2, const float* __restrict__ b2,
    const float* zin, int zstride, int din, int dh, int dout,
    float* hb /*[4][128] flat*/, float* gs /*[4][256] flat*/, int wid, int lane)
{
    for (int j = wid; j < dh; j += 8) {
        const float* wr = w1 + (size_t)j * din;
        float a0 = 0, a1 = 0, a2 = 0, a3 = 0;
        for (int i = lane; i < din; i += 32) {
            float w = wr[i];
            a0 += zin[i] * w;
            a1 += zin[zstride + i] * w;
            a2 += zin[2 * zstride + i] * w;
            a3 += zin[3 * zstride + i] * w;
        }
        a0 = warp_sum(a0); a1 = warp_sum(a1); a2 = warp_sum(a2); a3 = warp_sum(a3);
        if (lane == 0) {
            float b = b1[j];
            hb[0 * 128 + j] = fmaxf(a0 + b, 0.f);
            hb[1 * 128 + j] = fmaxf(a1 + b, 0.f);
            hb[2 * 128 + j] = fmaxf(a2 + b, 0.f);
            hb[3 * 128 + j] = fmaxf(a3 + b, 0.f);
        }
    }
    __syncthreads();
    for (int j = wid; j < dout; j += 8) {
        const float* wr = w2 + (size_t)j * dh;
        float a0 = 0, a1 = 0, a2 = 0, a3 = 0;
        for (int i = lane; i < dh; i += 32) {
            float w = wr[i];
            a0 += hb[0 * 128 + i] * w;
            a1 += hb[1 * 128 + i] * w;
            a2 += hb[2 * 128 + i] * w;
            a3 += hb[3 * 128 + i] * w;
        }
        a0 = warp_sum(a0); a1 = warp_sum(a1); a2 = warp_sum(a2); a3 = warp_sum(a3);
        if (lane == 0) {
            float b = b2[j];
            gs[0 * 256 + j] += 1.f / (1.f + expf(-(a0 + b)));
            gs[1 * 256 + j] += 1.f / (1.f + expf(-(a1 + b)));
            gs[2 * 256 + j] += 1.f / (1.f + expf(-(a2 + b)));
            gs[3 * 256 + j] += 1.f / (1.f + expf(-(a3 + b)));
        }
    }
    __syncthreads();
}

__global__ __launch_bounds__(256)
void mlp_kernel(
    const float* __restrict__ fs_w1,  const float* __restrict__ fs_b1,
    const float* __restrict__ fs_w2,  const float* __restrict__ fs_b2,
    const float* __restrict__ fsa_w1, const float* __restrict__ fsa_b1,
    const float* __restrict__ fsa_w2, const float* __restrict__ fsa_b2,
    const float* __restrict__ fsm_w1, const float* __restrict__ fsm_b1,
    const float* __restrict__ fsm_w2, const float* __restrict__ fsm_b2,
    const float* __restrict__ ft_w1,  const float* __restrict__ ft_b1,
    const float* __restrict__ ft_w2,  const float* __restrict__ ft_b2,
    const float* __restrict__ fta_w1, const float* __restrict__ fta_b1,
    const float* __restrict__ fta_w2, const float* __restrict__ fta_b2,
    const float* __restrict__ ftm_w1, const float* __restrict__ ftm_b1,
    const float* __restrict__ ftm_w2, const float* __restrict__ ftm_b2)
{
    __shared__ float ngs[4][128], ngt[4][128];
    __shared__ float zc[4][512];            // [zs | zt]
    __shared__ float za[4][256], zm[4][256];
    __shared__ float hbuf[4][128];
    __shared__ float gsum[2][4][256];
    __shared__ float redw[8];

    const int tid  = threadIdx.x;
    const int lane = tid & 31;
    const int wid  = tid >> 5;
    const int r0   = blockIdx.x * 4;
    const int half = tid >> 7;              // 0: student, 1: teacher
    const int b    = tid & 127;

    // Step 1: row-normalized Gram rows (both matrices in parallel)
    for (int r = 0; r < 4; r++) {
        int rowi = r0 + r;
        float v = g_gram[half][rowi][b];
        float ss = warp_sum(v * v);
        if (lane == 0) redw[wid] = ss;
        __syncthreads();
        float nrm = sqrtf(redw[half * 4 + 0] + redw[half * 4 + 1] +
                          redw[half * 4 + 2] + redw[half * 4 + 3]);
        float inv = 1.f / fmaxf(nrm, 1e-12f);
        if (half) ngt[r][b] = v * inv; else ngs[r][b] = v * inv;
        __syncthreads();
    }

    // Step 2: zs = normG_s @ y_s, zt = normG_t @ y_t  (thread = channel c)
    const float inv784 = 1.f / 784.f;
    const int c = tid;
    float zs0 = 0, zs1 = 0, zs2 = 0, zs3 = 0;
    for (int bb = 0; bb < 128; bb++) {
        float yv = g_pool[0][bb][c] * inv784;
        zs0 += ngs[0][bb] * yv; zs1 += ngs[1][bb] * yv;
        zs2 += ngs[2][bb] * yv; zs3 += ngs[3][bb] * yv;
    }
    float zt0 = 0, zt1 = 0, zt2 = 0, zt3 = 0;
    for (int bb = 0; bb < 128; bb++) {
        float yv = g_pool[1][bb][c] * inv784;
        zt0 += ngt[0][bb] * yv; zt1 += ngt[1][bb] * yv;
        zt2 += ngt[2][bb] * yv; zt3 += ngt[3][bb] * yv;
    }
    zc[0][c] = zs0; zc[1][c] = zs1; zc[2][c] = zs2; zc[3][c] = zs3;
    zc[0][256 + c] = zt0; zc[1][256 + c] = zt1; zc[2][256 + c] = zt2; zc[3][256 + c] = zt3;
    za[0][c] = zs0 + zt0; za[1][c] = zs1 + zt1; za[2][c] = zs2 + zt2; za[3][c] = zs3 + zt3;
    zm[0][c] = zs0 * zt0; zm[1][c] = zs1 * zt1; zm[2][c] = zs2 * zt2; zm[3][c] = zs3 * zt3;
    #pragma unroll
    for (int m = 0; m < 2; m++)
        #pragma unroll
        for (int r = 0; r < 4; r++) gsum[m][r][c] = 0.f;
    __syncthreads();

    // Step 3: six MLPs
    run_mlp(fs_w1,  fs_b1,  fs_w2,  fs_b2,  &zc[0][0], 512, 512, 128, 256,
            &hbuf[0][0], &gsum[0][0][0], wid, lane);
    run_mlp(fsa_w1, fsa_b1, fsa_w2, fsa_b2, &za[0][0], 256, 256, 64, 256,
            &hbuf[0][0], &gsum[0][0][0], wid, lane);
    run_mlp(fsm_w1, fsm_b1, fsm_w2, fsm_b2, &zm[0][0], 256, 256, 64, 256,
            &hbuf[0][0], &gsum[0][0][0], wid, lane);
    run_mlp(ft_w1,  ft_b1,  ft_w2,  ft_b2,  &zc[0][0], 512, 512, 128, 256,
            &hbuf[0][0], &gsum[1][0][0], wid, lane);
    run_mlp(fta_w1, fta_b1, fta_w2, fta_b2, &za[0][0], 256, 256, 64, 256,
            &hbuf[0][0], &gsum[1][0][0], wid, lane);
    run_mlp(ftm_w1, ftm_b1, ftm_w2, ftm_b2, &zm[0][0], 256, 256, 64, 256,
            &hbuf[0][0], &gsum[1][0][0], wid, lane);

    // Step 4: write gates
    #pragma unroll
    for (int m = 0; m < 2; m++)
        #pragma unroll
        for (int r = 0; r < 4; r++)
            g_gate[m][r0 + r][c] = gsum[m][r][c];
}

// ---------------------------------------------------------------------------
// Kernel 3: out = gate ⊙ x  (both tensors; float4 granularity)
// ---------------------------------------------------------------------------
#define PERQ 6422528            // float4 per tensor (128*256*784/4)
__global__ __launch_bounds__(256)
void scale_kernel(const float4* __restrict__ s, const float4* __restrict__ t,
                  float4* __restrict__ out) {
    unsigned idx = blockIdx.x * 256u + threadIdx.x;
    int m = idx >= PERQ;
    unsigned j = idx - (unsigned)m * PERQ;
    unsigned bc = j / 196u;                            // 196 float4 per (b,c)
    float g = g_gate[m][bc >> 8][bc & 255];
    float4 v = m ? t[j] : s[j];
    out[idx] = make_float4(g * v.x, g * v.y, g * v.z, g * v.w);
}

// ---------------------------------------------------------------------------
// Launch
// ---------------------------------------------------------------------------
extern "C" void kernel_launch(void* const* d_in, const int* in_sizes, int n_in,
                              void* d_out, int out_size) {
    const float* s = (const float*)d_in[0];
    const float* t = (const float*)d_in[1];
    const float* w[24];
    for (int i = 0; i < 24; i++) w[i] = (const float*)d_in[2 + i];

    zero_kernel<<<256, 256>>>();
    gram_kernel<<<dim3(GRIDX, 2), 256>>>(s, t);
    mlp_kernel<<<32, 256>>>(
        w[0],  w[1],  w[2],  w[3],
        w[4],  w[5],  w[6],  w[7],
        w[8],  w[9],  w[10], w[11],
        w[12], w[13], w[14], w[15],
        w[16], w[17], w[18], w[19],
        w[20], w[21], w[22], w[23]);
    scale_kernel<<<(2 * PERQ) / 256, 256>>>((const float4*)s, (const float4*)t,
                                            (float4*)d_out);
}

// round 6
// speedup vs baseline: 1.0485x; 1.0485x over previous
#include <cuda_runtime.h>
#include <cuda_bf16.h>
#include <cstdint>

// ---------------------------------------------------------------------------
// Problem constants
// ---------------------------------------------------------------------------
#define BATCH   128
#define CCH     256
#define HWSZ    784
#define KTOT    200704          // 256*784
#define CHUNK_K 64              // fp32 elements per row per chunk
#define TOTCH   3136            // KTOT / 64
#define GRIDX   148             // 148*21 + 28 = 3136 (first 28 CTAs take 22)
#define LDPAD   72              // bf16 per padded SMEM row (144 B)

// Device-global scratch (atomically accumulated; zeroed each call)
__device__ float g_gram[2][BATCH][BATCH];
__device__ float g_pool[2][BATCH][CCH];
__device__ float g_gate[2][BATCH][CCH];

// ---------------------------------------------------------------------------
// Helpers
// ---------------------------------------------------------------------------
__device__ __forceinline__ uint32_t smem_u32(const void* p) {
    uint32_t a;
    asm("{ .reg .u64 t; cvta.to.shared.u64 t, %1; cvt.u32.u64 %0, t; }"
        : "=r"(a) : "l"(p));
    return a;
}
__device__ __forceinline__ void ldmA(uint32_t a[4], uint32_t addr) {
    asm volatile("ldmatrix.sync.aligned.m8n8.x4.shared.b16 {%0,%1,%2,%3}, [%4];"
        : "=r"(a[0]), "=r"(a[1]), "=r"(a[2]), "=r"(a[3]) : "r"(addr));
}
__device__ __forceinline__ void ldmB(uint32_t b[2], uint32_t addr) {
    asm volatile("ldmatrix.sync.aligned.m8n8.x2.shared.b16 {%0,%1}, [%2];"
        : "=r"(b[0]), "=r"(b[1]) : "r"(addr));
}
__device__ __forceinline__ void mma16816(float c[4], const uint32_t a[4],
                                         const uint32_t b[2]) {
    asm volatile(
        "mma.sync.aligned.m16n8k16.row.col.f32.bf16.bf16.f32 "
        "{%0,%1,%2,%3}, {%4,%5,%6,%7}, {%8,%9}, {%0,%1,%2,%3};"
        : "+f"(c[0]), "+f"(c[1]), "+f"(c[2]), "+f"(c[3])
        : "r"(a[0]), "r"(a[1]), "r"(a[2]), "r"(a[3]), "r"(b[0]), "r"(b[1]));
}

// ---------------------------------------------------------------------------
// Kernel 0: zero scratch (g_gram + g_pool = 65536 floats)
// ---------------------------------------------------------------------------
__global__ void zero_kernel() {
    int i = blockIdx.x * 256 + threadIdx.x;
    if (i < 2 * BATCH * BATCH) (&g_gram[0][0][0])[i] = 0.f;
    (&g_pool[0][0][0])[i] = 0.f;
}

// ---------------------------------------------------------------------------
// Kernel 1: Gram + fused pooling.
//   grid (148, 2): blockIdx.y = matrix. Each CTA: 21-22 CONTIGUOUS chunks of
//   [128 rows x 64 fp32] -> bf16 SMEM tile used as both A and B operand.
//   Load mapping (coalesced): per LDG.128, lanes 0-15 cover one full 64-float
//   row segment, lanes 16-31 the next row -> 4 cache lines per LDG (nL=4).
//   Each thread owns rows {wid*16 + 2i + (lane>>4)}, i=0..7, for the whole
//   kernel -> per-row register pooling accumulators, flushed on channel change.
//   Compute: R1's warp tiling — warp w: rows (w&1)*64..+64, cols (w>>1)*32..+32,
//   4 A-frags x 4 B-frags -> 16 MMAs per k-step (max fragment reuse).
// ---------------------------------------------------------------------------
__global__ __launch_bounds__(256, 2)
void gram_kernel(const float* __restrict__ s, const float* __restrict__ t) {
    __shared__ __nv_bfloat16 tile[2][BATCH][LDPAD];

    const int mat  = blockIdx.y;
    const float* F = mat ? t : s;
    const int tid  = threadIdx.x;
    const int lane = tid & 31;
    const int wid  = tid >> 5;
    const int h    = lane >> 4;          // which of the 2 rows this lane loads
    const int li   = lane & 15;          // 4-float segment within the row

    const int bx     = blockIdx.x;
    const int start  = bx * 21 + (bx < 28 ? bx : 28);   // contiguous ranges
    const int nchunk = 21 + (bx < 28);

    // The 8 rows this thread loads (fixed for the whole kernel)
    const int   row0 = wid * 16 + h;
    const float* rbase = F + (size_t)row0 * KTOT + li * 4;

    float acc[4][4][4];
    #pragma unroll
    for (int mi = 0; mi < 4; mi++)
        #pragma unroll
        for (int ni = 0; ni < 4; ni++)
            #pragma unroll
            for (int r = 0; r < 4; r++) acc[mi][ni][r] = 0.f;

    // per-row-slot pooling accumulators
    float accP[8];
    int   chP[8];
    #pragma unroll
    for (int i = 0; i < 8; i++) { accP[i] = 0.f; chP[i] = -1; }

    uint2 pf[8];

    // prefetch chunk 0
    {
        const int kb = start * CHUNK_K;
        const int ch = (kb + li * 4) / HWSZ;
        #pragma unroll
        for (int i = 0; i < 8; i++) {
            float4 v = *(const float4*)(rbase + (size_t)(2 * i) * KTOT + kb);
            chP[i] = ch;
            accP[i] = (v.x + v.y) + (v.z + v.w);
            __nv_bfloat162 p0 = __float22bfloat162_rn(make_float2(v.x, v.y));
            __nv_bfloat162 p1 = __float22bfloat162_rn(make_float2(v.z, v.w));
            pf[i] = make_uint2(*(uint32_t*)&p0, *(uint32_t*)&p1);
        }
    }

    const int mbase = (wid & 1) * 64;
    const int nbase = (wid >> 1) * 32;
    const int a_row  = lane & 15;
    const int a_colo = (lane >> 4) * 8;
    const int lb     = lane & 15;

    for (int c = 0; c < nchunk; c++) {
        const int buf = c & 1;
        // store prefetched bf16 chunk (each thread: its 8 rows, cols li*4..+4)
        #pragma unroll
        for (int i = 0; i < 8; i++)
            *(uint2*)&tile[buf][row0 + 2 * i][li * 4] = pf[i];
        __syncthreads();   // store visible + previous compute on this buf done

        // prefetch next chunk (LDG latency overlaps MMA work below)
        if (c + 1 < nchunk) {
            const int kb = (start + c + 1) * CHUNK_K;
            const int ch = (kb + li * 4) / HWSZ;
            #pragma unroll
            for (int i = 0; i < 8; i++) {
                float4 v = *(const float4*)(rbase + (size_t)(2 * i) * KTOT + kb);
                if (ch != chP[i]) {
                    atomicAdd(&g_pool[mat][row0 + 2 * i][chP[i]], accP[i]);
                    accP[i] = 0.f; chP[i] = ch;
                }
                accP[i] += (v.x + v.y) + (v.z + v.w);
                __nv_bfloat162 p0 = __float22bfloat162_rn(make_float2(v.x, v.y));
                __nv_bfloat162 p1 = __float22bfloat162_rn(make_float2(v.z, v.w));
                pf[i] = make_uint2(*(uint32_t*)&p0, *(uint32_t*)&p1);
            }
        }

        const uint32_t base = smem_u32(&tile[buf][0][0]);
        #pragma unroll
        for (int ks = 0; ks < 4; ks++) {
            const int kc = ks * 16;
            uint32_t afr[4][4], bfr[4][2];
            #pragma unroll
            for (int mi = 0; mi < 4; mi++) {
                int r = mbase + mi * 16 + a_row;
                ldmA(afr[mi], base + (uint32_t)(r * LDPAD + kc + a_colo) * 2u);
            }
            #pragma unroll
            for (int ni = 0; ni < 4; ni++) {
                int r = nbase + ni * 8 + (lb & 7);
                int col = kc + (lb >> 3) * 8;
                ldmB(bfr[ni], base + (uint32_t)(r * LDPAD + col) * 2u);
            }
            #pragma unroll
            for (int mi = 0; mi < 4; mi++)
                #pragma unroll
                for (int ni = 0; ni < 4; ni++)
                    mma16816(acc[mi][ni], afr[mi], bfr[ni]);
        }
    }

    // flush pooling remainders
    #pragma unroll
    for (int i = 0; i < 8; i++)
        if (chP[i] >= 0) atomicAdd(&g_pool[mat][row0 + 2 * i][chP[i]], accP[i]);

    // epilogue: atomic-reduce partial G
    const int mrow = lane >> 2;
    const int ncol = 2 * (lane & 3);
    #pragma unroll
    for (int mi = 0; mi < 4; mi++) {
        #pragma unroll
        for (int ni = 0; ni < 4; ni++) {
            int m = mbase + mi * 16 + mrow;
            int n = nbase + ni * 8 + ncol;
            atomicAdd(&g_gram[mat][m][n],         acc[mi][ni][0]);
            atomicAdd(&g_gram[mat][m][n + 1],     acc[mi][ni][1]);
            atomicAdd(&g_gram[mat][m + 8][n],     acc[mi][ni][2]);
            atomicAdd(&g_gram[mat][m + 8][n + 1], acc[mi][ni][3]);
        }
    }
}

// ---------------------------------------------------------------------------
// Kernel 2: normalize + z + 6 MLPs -> gates. 32 CTAs x 4 batch rows.
// Warp-cooperative dot products (coalesced weight reads).
// ---------------------------------------------------------------------------
__device__ __forceinline__ float warp_sum(float v) {
    #pragma unroll
    for (int o = 16; o; o >>= 1) v += __shfl_xor_sync(0xFFFFFFFFu, v, o);
    return v;
}

__device__ __forceinline__ void run_mlp(
    const float* __restrict__ w1, const float* __restrict__ b1,
    const float* __restrict__ w2, const float* __restrict__ b2,
    const float* zin, int zstride, int din, int dh, int dout,
    float* hb /*[4][128] flat*/, float* gs /*[4][256] flat*/, int wid, int lane)
{
    for (int j = wid; j < dh; j += 8) {
        const float* wr = w1 + (size_t)j * din;
        float a0 = 0, a1 = 0, a2 = 0, a3 = 0;
        for (int i = lane; i < din; i += 32) {
            float w = wr[i];
            a0 += zin[i] * w;
            a1 += zin[zstride + i] * w;
            a2 += zin[2 * zstride + i] * w;
            a3 += zin[3 * zstride + i] * w;
        }
        a0 = warp_sum(a0); a1 = warp_sum(a1); a2 = warp_sum(a2); a3 = warp_sum(a3);
        if (lane == 0) {
            float b = b1[j];
            hb[0 * 128 + j] = fmaxf(a0 + b, 0.f);
            hb[1 * 128 + j] = fmaxf(a1 + b, 0.f);
            hb[2 * 128 + j] = fmaxf(a2 + b, 0.f);
            hb[3 * 128 + j] = fmaxf(a3 + b, 0.f);
        }
    }
    __syncthreads();
    for (int j = wid; j < dout; j += 8) {
        const float* wr = w2 + (size_t)j * dh;
        float a0 = 0, a1 = 0, a2 = 0, a3 = 0;
        for (int i = lane; i < dh; i += 32) {
            float w = wr[i];
            a0 += hb[0 * 128 + i] * w;
            a1 += hb[1 * 128 + i] * w;
            a2 += hb[2 * 128 + i] * w;
            a3 += hb[3 * 128 + i] * w;
        }
        a0 = warp_sum(a0); a1 = warp_sum(a1); a2 = warp_sum(a2); a3 = warp_sum(a3);
        if (lane == 0) {
            float b = b2[j];
            gs[0 * 256 + j] += 1.f / (1.f + expf(-(a0 + b)));
            gs[1 * 256 + j] += 1.f / (1.f + expf(-(a1 + b)));
            gs[2 * 256 + j] += 1.f / (1.f + expf(-(a2 + b)));
            gs[3 * 256 + j] += 1.f / (1.f + expf(-(a3 + b)));
        }
    }
    __syncthreads();
}

__global__ __launch_bounds__(256)
void mlp_kernel(
    const float* __restrict__ fs_w1,  const float* __restrict__ fs_b1,
    const float* __restrict__ fs_w2,  const float* __restrict__ fs_b2,
    const float* __restrict__ fsa_w1, const float* __restrict__ fsa_b1,
    const float* __restrict__ fsa_w2, const float* __restrict__ fsa_b2,
    const float* __restrict__ fsm_w1, const float* __restrict__ fsm_b1,
    const float* __restrict__ fsm_w2, const float* __restrict__ fsm_b2,
    const float* __restrict__ ft_w1,  const float* __restrict__ ft_b1,
    const float* __restrict__ ft_w2,  const float* __restrict__ ft_b2,
    const float* __restrict__ fta_w1, const float* __restrict__ fta_b1,
    const float* __restrict__ fta_w2, const float* __restrict__ fta_b2,
    const float* __restrict__ ftm_w1, const float* __restrict__ ftm_b1,
    const float* __restrict__ ftm_w2, const float* __restrict__ ftm_b2)
{
    __shared__ float ngs[4][128], ngt[4][128];
    __shared__ float zc[4][512];            // [zs | zt]
    __shared__ float za[4][256], zm[4][256];
    __shared__ float hbuf[4][128];
    __shared__ float gsum[2][4][256];
    __shared__ float redw[8];

    const int tid  = threadIdx.x;
    const int lane = tid & 31;
    const int wid  = tid >> 5;
    const int r0   = blockIdx.x * 4;
    const int half = tid >> 7;              // 0: student, 1: teacher
    const int b    = tid & 127;

    // Step 1: row-normalized Gram rows (both matrices in parallel)
    for (int r = 0; r < 4; r++) {
        int rowi = r0 + r;
        float v = g_gram[half][rowi][b];
        float ss = warp_sum(v * v);
        if (lane == 0) redw[wid] = ss;
        __syncthreads();
        float nrm = sqrtf(redw[half * 4 + 0] + redw[half * 4 + 1] +
                          redw[half * 4 + 2] + redw[half * 4 + 3]);
        float inv = 1.f / fmaxf(nrm, 1e-12f);
        if (half) ngt[r][b] = v * inv; else ngs[r][b] = v * inv;
        __syncthreads();
    }

    // Step 2: zs = normG_s @ y_s, zt = normG_t @ y_t  (thread = channel c)
    const float inv784 = 1.f / 784.f;
    const int c = tid;
    float zs0 = 0, zs1 = 0, zs2 = 0, zs3 = 0;
    for (int bb = 0; bb < 128; bb++) {
        float yv = g_pool[0][bb][c] * inv784;
        zs0 += ngs[0][bb] * yv; zs1 += ngs[1][bb] * yv;
        zs2 += ngs[2][bb] * yv; zs3 += ngs[3][bb] * yv;
    }
    float zt0 = 0, zt1 = 0, zt2 = 0, zt3 = 0;
    for (int bb = 0; bb < 128; bb++) {
        float yv = g_pool[1][bb][c] * inv784;
        zt0 += ngt[0][bb] * yv; zt1 += ngt[1][bb] * yv;
        zt2 += ngt[2][bb] * yv; zt3 += ngt[3][bb] * yv;
    }
    zc[0][c] = zs0; zc[1][c] = zs1; zc[2][c] = zs2; zc[3][c] = zs3;
    zc[0][256 + c] = zt0; zc[1][256 + c] = zt1; zc[2][256 + c] = zt2; zc[3][256 + c] = zt3;
    za[0][c] = zs0 + zt0; za[1][c] = zs1 + zt1; za[2][c] = zs2 + zt2; za[3][c] = zs3 + zt3;
    zm[0][c] = zs0 * zt0; zm[1][c] = zs1 * zt1; zm[2][c] = zs2 * zt2; zm[3][c] = zs3 * zt3;
    #pragma unroll
    for (int m = 0; m < 2; m++)
        #pragma unroll
        for (int r = 0; r < 4; r++) gsum[m][r][c] = 0.f;
    __syncthreads();

    // Step 3: six MLPs
    run_mlp(fs_w1,  fs_b1,  fs_w2,  fs_b2,  &zc[0][0], 512, 512, 128, 256,
            &hbuf[0][0], &gsum[0][0][0], wid, lane);
    run_mlp(fsa_w1, fsa_b1, fsa_w2, fsa_b2, &za[0][0], 256, 256, 64, 256,
            &hbuf[0][0], &gsum[0][0][0], wid, lane);
    run_mlp(fsm_w1, fsm_b1, fsm_w2, fsm_b2, &zm[0][0], 256, 256, 64, 256,
            &hbuf[0][0], &gsum[0][0][0], wid, lane);
    run_mlp(ft_w1,  ft_b1,  ft_w2,  ft_b2,  &zc[0][0], 512, 512, 128, 256,
            &hbuf[0][0], &gsum[1][0][0], wid, lane);
    run_mlp(fta_w1, fta_b1, fta_w2, fta_b2, &za[0][0], 256, 256, 64, 256,
            &hbuf[0][0], &gsum[1][0][0], wid, lane);
    run_mlp(ftm_w1, ftm_b1, ftm_w2, ftm_b2, &zm[0][0], 256, 256, 64, 256,
            &hbuf[0][0], &gsum[1][0][0], wid, lane);

    // Step 4: write gates
    #pragma unroll
    for (int m = 0; m < 2; m++)
        #pragma unroll
        for (int r = 0; r < 4; r++)
            g_gate[m][r0 + r][c] = gsum[m][r][c];
}

// ---------------------------------------------------------------------------
// Kernel 3: out = gate ⊙ x  (both tensors; float4 granularity)
// ---------------------------------------------------------------------------
#define PERQ 6422528            // float4 per tensor (128*256*784/4)
__global__ __launch_bounds__(256)
void scale_kernel(const float4* __restrict__ s, const float4* __restrict__ t,
                  float4* __restrict__ out) {
    unsigned idx = blockIdx.x * 256u + threadIdx.x;
    int m = idx >= PERQ;
    unsigned j = idx - (unsigned)m * PERQ;
    unsigned bc = j / 196u;                            // 196 float4 per (b,c)
    float g = g_gate[m][bc >> 8][bc & 255];
    float4 v = m ? t[j] : s[j];
    out[idx] = make_float4(g * v.x, g * v.y, g * v.z, g * v.w);
}

// ---------------------------------------------------------------------------
// Launch
// ---------------------------------------------------------------------------
extern "C" void kernel_launch(void* const* d_in, const int* in_sizes, int n_in,
                              void* d_out, int out_size) {
    const float* s = (const float*)d_in[0];
    const float* t = (const float*)d_in[1];
    const float* w[24];
    for (int i = 0; i < 24; i++) w[i] = (const float*)d_in[2 + i];

    zero_kernel<<<256, 256>>>();
    gram_kernel<<<dim3(GRIDX, 2), 256>>>(s, t);
    mlp_kernel<<<32, 256>>>(
        w[0],  w[1],  w[2],  w[3],
        w[4],  w[5],  w[6],  w[7],
        w[8],  w[9],  w[10], w[11],
        w[12], w[13], w[14], w[15],
        w[16], w[17], w[18], w[19],
        w[20], w[21], w[22], w[23]);
    scale_kernel<<<(2 * PERQ) / 256, 256>>>((const float4*)s, (const float4*)t,
                                            (float4*)d_out);
}